// round 8
// baseline (speedup 1.0000x reference)
#include <cuda_runtime.h>
#include <math.h>

#define NNODES 100000
#define NEDGES 1200000
#define DIM 64
#define NCHUNK ((NNODES + 1023) / 1024)   // 98

typedef unsigned long long ull;

// ---------------- scratch (device globals) ----------------
__device__ float g_dinv [NNODES];            // rsqrt(deg+1)
__device__ int   g_deg  [NNODES];            // in-degree (dst only)
__device__ int   g_start[NNODES];            // CSR row start
__device__ int   g_cursor[NNODES];           // placement cursors
__device__ int   g_bsum [NCHUNK];
__device__ int   g_boff [NCHUNK];
__device__ int   g_csr  [NEDGES];            // src ids grouped by dst

// ---------------- helpers ----------------
__device__ __forceinline__ ull fma2(ull a, ull b, ull c) {
    ull d;
    asm("fma.rn.f32x2 %0, %1, %2, %3;" : "=l"(d) : "l"(a), "l"(b), "l"(c));
    return d;
}
__device__ __forceinline__ ull dup2(float s) {
    ull d; unsigned u = __float_as_uint(s);
    asm("mov.b64 %0, {%1, %1};" : "=l"(d) : "r"(u));
    return d;
}
__device__ __forceinline__ float2 unpack2(ull v) {
    unsigned lo, hi;
    asm("mov.b64 {%0, %1}, %2;" : "=r"(lo), "=r"(hi) : "l"(v));
    return make_float2(__uint_as_float(lo), __uint_as_float(hi));
}
__device__ __forceinline__ float eluf(float z) {
    return z > 0.0f ? z : expm1f(z);
}

// ---------------- CSR build ----------------
__global__ void k_zero_deg() {
    int i = blockIdx.x * blockDim.x + threadIdx.x;
    if (i < NNODES) g_deg[i] = 0;
}

__global__ void k_deg(const int* __restrict__ dst) {
    int e = blockIdx.x * blockDim.x + threadIdx.x;
    if (e < NEDGES) {
        unsigned d = (unsigned)dst[e];
        if (d < NNODES) atomicAdd(&g_deg[d], 1);
    }
}

__global__ void k_scan1() {
    __shared__ int s[256];
    int blk = blockIdx.x, tid = threadIdx.x;
    int base = blk * 1024 + tid * 4;
    int d0 = 0, d1 = 0, d2 = 0, d3 = 0;
    if (base + 0 < NNODES) d0 = g_deg[base + 0];
    if (base + 1 < NNODES) d1 = g_deg[base + 1];
    if (base + 2 < NNODES) d2 = g_deg[base + 2];
    if (base + 3 < NNODES) d3 = g_deg[base + 3];
    int sum = d0 + d1 + d2 + d3;
    s[tid] = sum;
    __syncthreads();
    for (int off = 1; off < 256; off <<= 1) {
        int add = (tid >= off) ? s[tid - off] : 0;
        __syncthreads();
        s[tid] += add;
        __syncthreads();
    }
    int incl = s[tid];
    int run = incl - sum;
    if (tid == 255) g_bsum[blk] = incl;
    if (base + 0 < NNODES) { g_start[base + 0] = run; run += d0; }
    if (base + 1 < NNODES) { g_start[base + 1] = run; run += d1; }
    if (base + 2 < NNODES) { g_start[base + 2] = run; run += d2; }
    if (base + 3 < NNODES) { g_start[base + 3] = run; }
}

__global__ void k_scan2() {
    __shared__ int s[128];
    int tid = threadIdx.x;
    int v = (tid < NCHUNK) ? g_bsum[tid] : 0;
    s[tid] = v;
    __syncthreads();
    for (int off = 1; off < 128; off <<= 1) {
        int add = (tid >= off) ? s[tid - off] : 0;
        __syncthreads();
        s[tid] += add;
        __syncthreads();
    }
    if (tid < NCHUNK) g_boff[tid] = s[tid] - v;
}

__global__ void k_scan3() {
    int i = blockIdx.x * blockDim.x + threadIdx.x;
    if (i < NNODES) {
        int v = g_start[i] + g_boff[i >> 10];
        g_start[i]  = v;
        g_cursor[i] = v;
        g_dinv[i]   = rsqrtf((float)g_deg[i] + 1.0f);
    }
}

__global__ void k_place(const int* __restrict__ src,
                        const int* __restrict__ dst) {
    int e = blockIdx.x * blockDim.x + threadIdx.x;
    if (e >= NEDGES) return;
    unsigned s = (unsigned)src[e];
    unsigned d = (unsigned)dst[e];
    if (s >= NNODES || d >= NNODES) return;
    int pos = atomicAdd(&g_cursor[d], 1);
    if (pos < NEDGES) g_csr[pos] = (int)s;
}

// ---------------- fused gather + matvec ----------------
// 512 threads, 128 nodes/block.
// Phase B: warp-per-node gather. 2 halves x 16 lanes; each half processes one
//   edge per iteration (lane q loads float4 q of x[src]) -> minimal L1 line
//   touches, warp-uniform loop bound. Cross-half shfl_xor reduce.
// inT row mapping is interleaved: row(t,k) = t*64 + (k&3)*16 + (k>>2), making
//   the store pattern (lanes stride 4 rows) only 2-way bank conflicted while
//   keeping node as the contiguous axis for phase C's packed loads.
// Phase C: packed f32x2 matvec + ELU + combine.
// SMEM: Ws 16384 + inT 33792 + nsum 128 = 50304 floats = 201216 B.
#define INPAD 132
__global__ void __launch_bounds__(512, 1)
k_fused(const float* __restrict__ x,
        const float* __restrict__ weights,
        const float* __restrict__ Wg,  const float* __restrict__ bg,
        const float* __restrict__ Wsl, const float* __restrict__ Wn,
        const float* __restrict__ bs,
        const float* __restrict__ Wi,  const float* __restrict__ bi,
        float* __restrict__ out) {
    extern __shared__ float sm[];
    float* Ws   = sm;                 // 16384
    float* inT  = sm + 16384;         // 33792
    float* nsum = inT + 33792;        // 128

    int tid = threadIdx.x;
    int nodeBase = blockIdx.x * 128;

    // ---- phase A: stage weights ----
    {
        float4* d4 = reinterpret_cast<float4*>(Ws);
        const float4* s0 = reinterpret_cast<const float4*>(Wg);
        const float4* s1 = reinterpret_cast<const float4*>(Wsl);
        const float4* s2 = reinterpret_cast<const float4*>(Wn);
        const float4* s3 = reinterpret_cast<const float4*>(Wi);
        for (int i = tid; i < 1024; i += 512) {
            d4[i]        = s0[i];
            d4[1024 + i] = s1[i];
            d4[2048 + i] = s2[i];
            d4[3072 + i] = s3[i];
        }
    }

    // ---- phase B: warp-per-node gather ----
    {
        int wrp  = tid >> 5;          // 0..15
        int lane = tid & 31;
        int half = lane >> 4;         // 0/1
        int q    = lane & 15;         // float4 index in 64-dim row
        unsigned hmask = 0xFFFFu << (half << 4);
        int srcLane = half << 4;
        const float4* x4 = reinterpret_cast<const float4*>(x);
        const float4 z = make_float4(0.f, 0.f, 0.f, 0.f);

        for (int ni = 0; ni < 8; ni++) {
            int node = wrp * 8 + ni;
            int gn = nodeBase + node;
            bool valid = gn < NNODES;
            int gns = valid ? gn : 0;
            int beg = g_start[gns];
            int deg = valid ? g_deg[gns] : 0;
            int end = beg + deg;

            float4 acc = z, accw = z;
            float swacc = 0.f;
            for (int i = beg + half; i < end; i += 2) {
                int sraw = 0; float draw = 0.f;
                if (q == 0) {
                    sraw = __ldg(g_csr + i);
                    draw = __ldg(g_dinv + sraw);
                }
                int s    = __shfl_sync(hmask, sraw, srcLane);
                float ds = __shfl_sync(hmask, draw, srcLane);
                float4 xv = __ldg(x4 + s * 16 + q);
                acc.x += xv.x; acc.y += xv.y; acc.z += xv.z; acc.w += xv.w;
                accw.x = fmaf(ds, xv.x, accw.x);
                accw.y = fmaf(ds, xv.y, accw.y);
                accw.z = fmaf(ds, xv.z, accw.z);
                accw.w = fmaf(ds, xv.w, accw.w);
                swacc += ds;
            }
            // cross-half reduce (warp reconverged here)
            acc.x  += __shfl_xor_sync(0xFFFFFFFFu, acc.x,  16);
            acc.y  += __shfl_xor_sync(0xFFFFFFFFu, acc.y,  16);
            acc.z  += __shfl_xor_sync(0xFFFFFFFFu, acc.z,  16);
            acc.w  += __shfl_xor_sync(0xFFFFFFFFu, acc.w,  16);
            accw.x += __shfl_xor_sync(0xFFFFFFFFu, accw.x, 16);
            accw.y += __shfl_xor_sync(0xFFFFFFFFu, accw.y, 16);
            accw.z += __shfl_xor_sync(0xFFFFFFFFu, accw.z, 16);
            accw.w += __shfl_xor_sync(0xFFFFFFFFu, accw.w, 16);
            swacc  += __shfl_xor_sync(0xFFFFFFFFu, swacc,  16);

            float di  = g_dinv[gns];
            float dsq = di * di;
            float invdeg = 1.0f / fmaxf((float)deg, 1.0f);
            if (lane == 0) nsum[node] = valid ? (di * swacc + dsq) : 0.0f;

            float4 xv = valid ? __ldg(x4 + gns * 16 + q) : z;
            float4 gc = make_float4(di * accw.x + dsq * xv.x,
                                    di * accw.y + dsq * xv.y,
                                    di * accw.z + dsq * xv.z,
                                    di * accw.w + dsq * xv.w);
            float4 mn = make_float4(invdeg * acc.x, invdeg * acc.y,
                                    invdeg * acc.z, invdeg * acc.w);
            float4 gi = make_float4(xv.x + acc.x, xv.y + acc.y,
                                    xv.z + acc.z, xv.w + acc.w);

            // half0 stores types 0 (gc), 1 (xv); half1 stores 2 (mn), 3 (gi).
            float a0 = half ? mn.x : gc.x, a1 = half ? mn.y : gc.y,
                  a2 = half ? mn.z : gc.z, a3 = half ? mn.w : gc.w;
            float b0 = half ? gi.x : xv.x, b1 = half ? gi.y : xv.y,
                  b2 = half ? gi.z : xv.z, b3 = half ? gi.w : xv.w;
            int t0 = half << 1;
            // row(t, k=q*4+j) = t*64 + j*16 + q ; addr = row*INPAD + node
            int baseA = (t0 * 64 + q) * INPAD + node;
            int baseB = baseA + 64 * INPAD;
            inT[baseA + 0 * 16 * INPAD] = a0;
            inT[baseA + 1 * 16 * INPAD] = a1;
            inT[baseA + 2 * 16 * INPAD] = a2;
            inT[baseA + 3 * 16 * INPAD] = a3;
            inT[baseB + 0 * 16 * INPAD] = b0;
            inT[baseB + 1 * 16 * INPAD] = b1;
            inT[baseB + 2 * 16 * INPAD] = b2;
            inT[baseB + 3 * 16 * INPAD] = b3;
        }
    }
    __syncthreads();

    // ---- phase C: packed f32x2 matvec ----
    int ng = tid & 31;   // node group: nodes ng*4 .. ng*4+3
    int jg = tid >> 5;   // output cols jg*4 .. jg*4+3 (warp-uniform)

    ull accG[8], accS[8], accI[8];
#pragma unroll
    for (int i = 0; i < 8; i++) { accG[i] = 0ull; accS[i] = 0ull; accI[i] = 0ull; }

#define DOMV(ACC, W, IN) {                                              \
    ull w0 = dup2((W).x), w1 = dup2((W).y),                             \
        w2 = dup2((W).z), w3 = dup2((W).w);                             \
    ACC[0] = fma2((IN).x, w0, ACC[0]); ACC[1] = fma2((IN).y, w0, ACC[1]); \
    ACC[2] = fma2((IN).x, w1, ACC[2]); ACC[3] = fma2((IN).y, w1, ACC[3]); \
    ACC[4] = fma2((IN).x, w2, ACC[4]); ACC[5] = fma2((IN).y, w2, ACC[5]); \
    ACC[6] = fma2((IN).x, w3, ACC[6]); ACC[7] = fma2((IN).y, w3, ACC[7]); }

#pragma unroll 4
    for (int k = 0; k < 64; k++) {
        int krow = ((k & 3) << 4) + (k >> 2);   // interleaved row mapping
        float4 wg  = *reinterpret_cast<const float4*>(&Ws[k * 64 + jg * 4]);
        float4 wsl = *reinterpret_cast<const float4*>(&Ws[4096 + k * 64 + jg * 4]);
        float4 wn  = *reinterpret_cast<const float4*>(&Ws[8192 + k * 64 + jg * 4]);
        float4 wi  = *reinterpret_cast<const float4*>(&Ws[12288 + k * 64 + jg * 4]);

        ulonglong2 i0 = *reinterpret_cast<const ulonglong2*>(&inT[(0 * 64 + krow) * INPAD + ng * 4]);
        ulonglong2 i1 = *reinterpret_cast<const ulonglong2*>(&inT[(1 * 64 + krow) * INPAD + ng * 4]);
        ulonglong2 i2 = *reinterpret_cast<const ulonglong2*>(&inT[(2 * 64 + krow) * INPAD + ng * 4]);
        ulonglong2 i3 = *reinterpret_cast<const ulonglong2*>(&inT[(3 * 64 + krow) * INPAD + ng * 4]);

        DOMV(accG, wg,  i0);
        DOMV(accS, wsl, i1);
        DOMV(accS, wn,  i2);
        DOMV(accI, wi,  i3);
    }
#undef DOMV

    // ---- epilogue ----
    float w0 = __ldg(weights + 0);
    float w1 = __ldg(weights + 1);
    float w2 = __ldg(weights + 2);
    float4 bgv = __ldg(reinterpret_cast<const float4*>(bg) + jg);
    float4 bsv = __ldg(reinterpret_cast<const float4*>(bs) + jg);
    float4 biv = __ldg(reinterpret_cast<const float4*>(bi) + jg);
    float bga[4] = {bgv.x, bgv.y, bgv.z, bgv.w};
    float bsa[4] = {bsv.x, bsv.y, bsv.z, bsv.w};
    float bia[4] = {biv.x, biv.y, biv.z, biv.w};

#pragma unroll
    for (int i = 0; i < 4; i++) {
        int p = i >> 1, h = i & 1;
        int nloc = ng * 4 + i;
        int gn = nodeBase + nloc;
        if (gn >= NNODES) continue;
        float ns = nsum[nloc];
        float o[4];
#pragma unroll
        for (int j = 0; j < 4; j++) {
            float2 fg = unpack2(accG[j * 2 + p]);
            float2 fs = unpack2(accS[j * 2 + p]);
            float2 fi = unpack2(accI[j * 2 + p]);
            float vg = (h ? fg.y : fg.x) + bga[j] * ns;
            float vs = (h ? fs.y : fs.x) + bsa[j];
            float vi = (h ? fi.y : fi.x) + bia[j];
            o[j] = w0 * eluf(vg) + w1 * eluf(vs) + w2 * eluf(vi);
        }
        *reinterpret_cast<float4*>(&out[gn * 64 + jg * 4]) =
            make_float4(o[0], o[1], o[2], o[3]);
    }
}

// ---------------- launch ----------------
extern "C" void kernel_launch(void* const* d_in, const int* in_sizes, int n_in,
                              void* d_out, int out_size) {
    const float* x       = (const float*)d_in[0];
    // d_in[1] = x0 (unused by reference ops)
    const float* weights = (const float*)d_in[2];
    const int*   ei      = (const int*)d_in[3];   // int32
    const float* Wg      = (const float*)d_in[4];
    const float* bg      = (const float*)d_in[5];
    const float* Wsl     = (const float*)d_in[6];
    const float* Wn      = (const float*)d_in[7];
    const float* bs      = (const float*)d_in[8];
    const float* Wi      = (const float*)d_in[9];
    const float* bi      = (const float*)d_in[10];

    const int* src = ei;
    const int* dst = ei + NEDGES;

    k_zero_deg<<<(NNODES + 255) / 256, 256>>>();
    k_deg<<<(NEDGES + 255) / 256, 256>>>(dst);
    k_scan1<<<NCHUNK, 256>>>();
    k_scan2<<<1, 128>>>();
    k_scan3<<<(NNODES + 255) / 256, 256>>>();
    k_place<<<(NEDGES + 255) / 256, 256>>>(src, dst);
    {
        const int smem = 201216;
        (void)cudaFuncSetAttribute(k_fused, cudaFuncAttributeMaxDynamicSharedMemorySize, smem);
        int blocks = (NNODES + 127) / 128;  // 782
        k_fused<<<blocks, 512, smem>>>(x, weights, Wg, bg, Wsl, Wn, bs, Wi, bi,
                                       (float*)d_out);
    }
}

// round 9
// speedup vs baseline: 1.5006x; 1.5006x over previous
#include <cuda_runtime.h>
#include <math.h>

#define NNODES 100000
#define NEDGES 1200000
#define DIM 64
#define NCHUNK ((NNODES + 1023) / 1024)   // 98

typedef unsigned long long ull;

// ---------------- scratch (device globals) ----------------
__device__ float g_dinv [NNODES];            // rsqrt(deg+1)
__device__ int   g_deg  [NNODES];            // in-degree (dst only)
__device__ int   g_start[NNODES];            // CSR row start
__device__ int   g_cursor[NNODES];           // placement cursors
__device__ int   g_bsum [NCHUNK];
__device__ int   g_boff [NCHUNK];
__device__ int   g_csr  [NEDGES];            // src ids grouped by dst

// ---------------- helpers ----------------
__device__ __forceinline__ ull fma2(ull a, ull b, ull c) {
    ull d;
    asm("fma.rn.f32x2 %0, %1, %2, %3;" : "=l"(d) : "l"(a), "l"(b), "l"(c));
    return d;
}
__device__ __forceinline__ ull dup2(float s) {
    ull d; unsigned u = __float_as_uint(s);
    asm("mov.b64 %0, {%1, %1};" : "=l"(d) : "r"(u));
    return d;
}
__device__ __forceinline__ float2 unpack2(ull v) {
    unsigned lo, hi;
    asm("mov.b64 {%0, %1}, %2;" : "=r"(lo), "=r"(hi) : "l"(v));
    return make_float2(__uint_as_float(lo), __uint_as_float(hi));
}
__device__ __forceinline__ float eluf(float z) {
    return z > 0.0f ? z : expm1f(z);
}

// ---------------- CSR build ----------------
__global__ void k_zero_deg() {
    int i = blockIdx.x * blockDim.x + threadIdx.x;
    if (i < NNODES) g_deg[i] = 0;
}

__global__ void k_deg(const int* __restrict__ dst) {
    int e = blockIdx.x * blockDim.x + threadIdx.x;
    if (e < NEDGES) {
        unsigned d = (unsigned)dst[e];
        if (d < NNODES) atomicAdd(&g_deg[d], 1);
    }
}

__global__ void k_scan1() {
    __shared__ int s[256];
    int blk = blockIdx.x, tid = threadIdx.x;
    int base = blk * 1024 + tid * 4;
    int d0 = 0, d1 = 0, d2 = 0, d3 = 0;
    if (base + 0 < NNODES) d0 = g_deg[base + 0];
    if (base + 1 < NNODES) d1 = g_deg[base + 1];
    if (base + 2 < NNODES) d2 = g_deg[base + 2];
    if (base + 3 < NNODES) d3 = g_deg[base + 3];
    int sum = d0 + d1 + d2 + d3;
    s[tid] = sum;
    __syncthreads();
    for (int off = 1; off < 256; off <<= 1) {
        int add = (tid >= off) ? s[tid - off] : 0;
        __syncthreads();
        s[tid] += add;
        __syncthreads();
    }
    int incl = s[tid];
    int run = incl - sum;
    if (tid == 255) g_bsum[blk] = incl;
    if (base + 0 < NNODES) { g_start[base + 0] = run; run += d0; }
    if (base + 1 < NNODES) { g_start[base + 1] = run; run += d1; }
    if (base + 2 < NNODES) { g_start[base + 2] = run; run += d2; }
    if (base + 3 < NNODES) { g_start[base + 3] = run; }
}

__global__ void k_scan2() {
    __shared__ int s[128];
    int tid = threadIdx.x;
    int v = (tid < NCHUNK) ? g_bsum[tid] : 0;
    s[tid] = v;
    __syncthreads();
    for (int off = 1; off < 128; off <<= 1) {
        int add = (tid >= off) ? s[tid - off] : 0;
        __syncthreads();
        s[tid] += add;
        __syncthreads();
    }
    if (tid < NCHUNK) g_boff[tid] = s[tid] - v;
}

__global__ void k_scan3() {
    int i = blockIdx.x * blockDim.x + threadIdx.x;
    if (i < NNODES) {
        int v = g_start[i] + g_boff[i >> 10];
        g_start[i]  = v;
        g_cursor[i] = v;
        g_dinv[i]   = rsqrtf((float)g_deg[i] + 1.0f);
    }
}

__global__ void k_place(const int* __restrict__ src,
                        const int* __restrict__ dst) {
    int e = blockIdx.x * blockDim.x + threadIdx.x;
    if (e >= NEDGES) return;
    unsigned s = (unsigned)src[e];
    unsigned d = (unsigned)dst[e];
    if (s >= NNODES || d >= NNODES) return;
    int pos = atomicAdd(&g_cursor[d], 1);
    if (pos < NEDGES) g_csr[pos] = (int)s;
}

// ---------------- fused gather + matvec (R7 layout + 2x pipelined gather) --
// 512 threads, 128 nodes/block. Phase B: quads (4 threads) gather neighbor
// sums in registers (edge loop unrolled x2 for MLP), transform, store
// transposed tiles in smem. Phase C: packed f32x2 matvec + ELU + combine.
// SMEM: Ws 16384 + inT 33792 + nsum 128 = 50304 floats = 201216 B.
#define INPAD 132
__global__ void __launch_bounds__(512, 1)
k_fused(const float* __restrict__ x,
        const float* __restrict__ weights,
        const float* __restrict__ Wg,  const float* __restrict__ bg,
        const float* __restrict__ Wsl, const float* __restrict__ Wn,
        const float* __restrict__ bs,
        const float* __restrict__ Wi,  const float* __restrict__ bi,
        float* __restrict__ out) {
    extern __shared__ float sm[];
    float* Ws   = sm;                 // 16384
    float* inT  = sm + 16384;         // 33792
    float* nsum = inT + 33792;        // 128

    int tid = threadIdx.x;
    int nodeBase = blockIdx.x * 128;

    // ---- phase A: stage weights ----
    {
        float4* d4 = reinterpret_cast<float4*>(Ws);
        const float4* s0 = reinterpret_cast<const float4*>(Wg);
        const float4* s1 = reinterpret_cast<const float4*>(Wsl);
        const float4* s2 = reinterpret_cast<const float4*>(Wn);
        const float4* s3 = reinterpret_cast<const float4*>(Wi);
        for (int i = tid; i < 1024; i += 512) {
            d4[i]        = s0[i];
            d4[1024 + i] = s1[i];
            d4[2048 + i] = s2[i];
            d4[3072 + i] = s3[i];
        }
    }

    // ---- phase B: gather per quad (2-edge pipelined), transform, write inT --
    {
        int node = tid >> 2;          // 0..127
        int part = tid & 3;           // 16 dims each
        int lane = tid & 31;
        unsigned qmask = 0xFu << (lane & ~3);
        int qbase = lane & ~3;
        int gn = nodeBase + node;
        bool valid = gn < NNODES;
        int gns = valid ? gn : 0;

        int beg = g_start[gns];
        int deg = valid ? g_deg[gns] : 0;
        int end = beg + deg;

        float4 acc[4], accw[4];
#pragma unroll
        for (int j = 0; j < 4; j++) {
            acc[j]  = make_float4(0.f, 0.f, 0.f, 0.f);
            accw[j] = make_float4(0.f, 0.f, 0.f, 0.f);
        }
        float swacc = 0.0f;

        const float4* x4 = reinterpret_cast<const float4*>(x);
        int i = beg;
        for (; i + 1 < end; i += 2) {
            int sraw0 = 0, sraw1 = 0; float draw0 = 0.f, draw1 = 0.f;
            if (part == 0) {
                sraw0 = __ldg(g_csr + i);
                sraw1 = __ldg(g_csr + i + 1);
                draw0 = __ldg(g_dinv + sraw0);
                draw1 = __ldg(g_dinv + sraw1);
            }
            int s0    = __shfl_sync(qmask, sraw0, qbase);
            int s1    = __shfl_sync(qmask, sraw1, qbase);
            float ds0 = __shfl_sync(qmask, draw0, qbase);
            float ds1 = __shfl_sync(qmask, draw1, qbase);
            swacc += ds0 + ds1;
            const float4* xs0 = x4 + s0 * 16 + part * 4;
            const float4* xs1 = x4 + s1 * 16 + part * 4;
#pragma unroll
            for (int j = 0; j < 4; j++) {
                float4 a = __ldg(xs0 + j);
                float4 b = __ldg(xs1 + j);
                acc[j].x += a.x + b.x;
                acc[j].y += a.y + b.y;
                acc[j].z += a.z + b.z;
                acc[j].w += a.w + b.w;
                accw[j].x = fmaf(ds0, a.x, fmaf(ds1, b.x, accw[j].x));
                accw[j].y = fmaf(ds0, a.y, fmaf(ds1, b.y, accw[j].y));
                accw[j].z = fmaf(ds0, a.z, fmaf(ds1, b.z, accw[j].z));
                accw[j].w = fmaf(ds0, a.w, fmaf(ds1, b.w, accw[j].w));
            }
        }
        if (i < end) {   // tail edge
            int sraw = 0; float draw = 0.f;
            if (part == 0) {
                sraw = __ldg(g_csr + i);
                draw = __ldg(g_dinv + sraw);
            }
            int s    = __shfl_sync(qmask, sraw, qbase);
            float ds = __shfl_sync(qmask, draw, qbase);
            swacc += ds;
            const float4* xs = x4 + s * 16 + part * 4;
#pragma unroll
            for (int j = 0; j < 4; j++) {
                float4 a = __ldg(xs + j);
                acc[j].x += a.x; acc[j].y += a.y;
                acc[j].z += a.z; acc[j].w += a.w;
                accw[j].x = fmaf(ds, a.x, accw[j].x);
                accw[j].y = fmaf(ds, a.y, accw[j].y);
                accw[j].z = fmaf(ds, a.z, accw[j].z);
                accw[j].w = fmaf(ds, a.w, accw[j].w);
            }
        }

        float di  = g_dinv[gns];
        float dsq = di * di;
        float invdeg = 1.0f / fmaxf((float)deg, 1.0f);
        if (part == 0) nsum[node] = valid ? (di * swacc + dsq) : 0.0f;

        float4 z = make_float4(0.f, 0.f, 0.f, 0.f);
#pragma unroll
        for (int j = 0; j < 4; j++) {
            float4 xv = valid ? __ldg(x4 + gns * 16 + part * 4 + j) : z;
            float4 ag = valid ? acc[j]  : z;
            float4 aw = valid ? accw[j] : z;
            float4 gc = make_float4(di * aw.x + dsq * xv.x,
                                    di * aw.y + dsq * xv.y,
                                    di * aw.z + dsq * xv.z,
                                    di * aw.w + dsq * xv.w);
            float4 mn = make_float4(invdeg * ag.x, invdeg * ag.y,
                                    invdeg * ag.z, invdeg * ag.w);
            float4 gi = make_float4(xv.x + ag.x, xv.y + ag.y,
                                    xv.z + ag.z, xv.w + ag.w);
            int kb = part * 16 + j * 4;
#define ST(t, kk, v) inT[((t) * 64 + (kk)) * INPAD + node] = (v)
            ST(0, kb + 0, gc.x); ST(0, kb + 1, gc.y); ST(0, kb + 2, gc.z); ST(0, kb + 3, gc.w);
            ST(1, kb + 0, xv.x); ST(1, kb + 1, xv.y); ST(1, kb + 2, xv.z); ST(1, kb + 3, xv.w);
            ST(2, kb + 0, mn.x); ST(2, kb + 1, mn.y); ST(2, kb + 2, mn.z); ST(2, kb + 3, mn.w);
            ST(3, kb + 0, gi.x); ST(3, kb + 1, gi.y); ST(3, kb + 2, gi.z); ST(3, kb + 3, gi.w);
#undef ST
        }
    }
    __syncthreads();

    // ---- phase C: packed f32x2 matvec ----
    int ng = tid & 31;   // node group: nodes ng*4 .. ng*4+3
    int jg = tid >> 5;   // output cols jg*4 .. jg*4+3 (warp-uniform)

    ull accG[8], accS[8], accI[8];
#pragma unroll
    for (int i = 0; i < 8; i++) { accG[i] = 0ull; accS[i] = 0ull; accI[i] = 0ull; }

#define DOMV(ACC, W, IN) {                                              \
    ull w0 = dup2((W).x), w1 = dup2((W).y),                             \
        w2 = dup2((W).z), w3 = dup2((W).w);                             \
    ACC[0] = fma2((IN).x, w0, ACC[0]); ACC[1] = fma2((IN).y, w0, ACC[1]); \
    ACC[2] = fma2((IN).x, w1, ACC[2]); ACC[3] = fma2((IN).y, w1, ACC[3]); \
    ACC[4] = fma2((IN).x, w2, ACC[4]); ACC[5] = fma2((IN).y, w2, ACC[5]); \
    ACC[6] = fma2((IN).x, w3, ACC[6]); ACC[7] = fma2((IN).y, w3, ACC[7]); }

#pragma unroll 4
    for (int k = 0; k < 64; k++) {
        float4 wg  = *reinterpret_cast<const float4*>(&Ws[k * 64 + jg * 4]);
        float4 wsl = *reinterpret_cast<const float4*>(&Ws[4096 + k * 64 + jg * 4]);
        float4 wn  = *reinterpret_cast<const float4*>(&Ws[8192 + k * 64 + jg * 4]);
        float4 wi  = *reinterpret_cast<const float4*>(&Ws[12288 + k * 64 + jg * 4]);

        ulonglong2 i0 = *reinterpret_cast<const ulonglong2*>(&inT[(0 * 64 + k) * INPAD + ng * 4]);
        ulonglong2 i1 = *reinterpret_cast<const ulonglong2*>(&inT[(1 * 64 + k) * INPAD + ng * 4]);
        ulonglong2 i2 = *reinterpret_cast<const ulonglong2*>(&inT[(2 * 64 + k) * INPAD + ng * 4]);
        ulonglong2 i3 = *reinterpret_cast<const ulonglong2*>(&inT[(3 * 64 + k) * INPAD + ng * 4]);

        DOMV(accG, wg,  i0);
        DOMV(accS, wsl, i1);
        DOMV(accS, wn,  i2);
        DOMV(accI, wi,  i3);
    }
#undef DOMV

    // ---- epilogue ----
    float w0 = __ldg(weights + 0);
    float w1 = __ldg(weights + 1);
    float w2 = __ldg(weights + 2);
    float4 bgv = __ldg(reinterpret_cast<const float4*>(bg) + jg);
    float4 bsv = __ldg(reinterpret_cast<const float4*>(bs) + jg);
    float4 biv = __ldg(reinterpret_cast<const float4*>(bi) + jg);
    float bga[4] = {bgv.x, bgv.y, bgv.z, bgv.w};
    float bsa[4] = {bsv.x, bsv.y, bsv.z, bsv.w};
    float bia[4] = {biv.x, biv.y, biv.z, biv.w};

#pragma unroll
    for (int i = 0; i < 4; i++) {
        int p = i >> 1, h = i & 1;
        int nloc = ng * 4 + i;
        int gn = nodeBase + nloc;
        if (gn >= NNODES) continue;
        float ns = nsum[nloc];
        float o[4];
#pragma unroll
        for (int j = 0; j < 4; j++) {
            float2 fg = unpack2(accG[j * 2 + p]);
            float2 fs = unpack2(accS[j * 2 + p]);
            float2 fi = unpack2(accI[j * 2 + p]);
            float vg = (h ? fg.y : fg.x) + bga[j] * ns;
            float vs = (h ? fs.y : fs.x) + bsa[j];
            float vi = (h ? fi.y : fi.x) + bia[j];
            o[j] = w0 * eluf(vg) + w1 * eluf(vs) + w2 * eluf(vi);
        }
        *reinterpret_cast<float4*>(&out[gn * 64 + jg * 4]) =
            make_float4(o[0], o[1], o[2], o[3]);
    }
}

// ---------------- launch ----------------
extern "C" void kernel_launch(void* const* d_in, const int* in_sizes, int n_in,
                              void* d_out, int out_size) {
    const float* x       = (const float*)d_in[0];
    // d_in[1] = x0 (unused by reference ops)
    const float* weights = (const float*)d_in[2];
    const int*   ei      = (const int*)d_in[3];   // int32
    const float* Wg      = (const float*)d_in[4];
    const float* bg      = (const float*)d_in[5];
    const float* Wsl     = (const float*)d_in[6];
    const float* Wn      = (const float*)d_in[7];
    const float* bs      = (const float*)d_in[8];
    const float* Wi      = (const float*)d_in[9];
    const float* bi      = (const float*)d_in[10];

    const int* src = ei;
    const int* dst = ei + NEDGES;

    k_zero_deg<<<(NNODES + 255) / 256, 256>>>();
    k_deg<<<(NEDGES + 255) / 256, 256>>>(dst);
    k_scan1<<<NCHUNK, 256>>>();
    k_scan2<<<1, 128>>>();
    k_scan3<<<(NNODES + 255) / 256, 256>>>();
    k_place<<<(NEDGES + 255) / 256, 256>>>(src, dst);
    {
        const int smem = 201216;
        (void)cudaFuncSetAttribute(k_fused, cudaFuncAttributeMaxDynamicSharedMemorySize, smem);
        int blocks = (NNODES + 127) / 128;  // 782
        k_fused<<<blocks, 512, smem>>>(x, weights, Wg, bg, Wsl, Wn, bs, Wi, bi,
                                       (float*)d_out);
    }
}